// round 9
// baseline (speedup 1.0000x reference)
#include <cuda_runtime.h>
#include <cuda_bf16.h>
#include <cstdint>
#include <cstddef>

#define BDIM 4
#define SDIM 8192
#define DDIM 768
#define NSUB 4096
#define EG   32768
#define NPAIR 8   // p = sample*2 + graph (graph 0 = edges, 1 = nodes)

// ---------------- static device scratch ----------------
__device__ int   g_deg [NPAIR][NSUB];
__device__ int   g_off [NPAIR][NSUB + 1];
__device__ int   g_cur [NPAIR][NSUB];
__device__ float g_dinv[NPAIR][NSUB];
__device__ int   g_ctok[NPAIR][EG];    // precomputed: map[src] (global token row)
__device__ float g_cw  [NPAIR][EG];    // precomputed: dinv[src]
__device__ unsigned char g_flag[BDIM][SDIM];   // 1 = token covered by e2t
__device__ __align__(16) __nv_bfloat16 g_agg[2][(size_t)BDIM * NSUB * DDIM];
__device__ __align__(16) __nv_bfloat16 g_Wt [2][DDIM * DDIM];   // W^T bf16: [n][k]

// ---------------- PTX helpers (sm_80-era features only) ----------------
__device__ __forceinline__ uint32_t smem_u32(const void* p) {
    uint32_t a;
    asm("{ .reg .u64 t; cvta.to.shared.u64 t, %1; cvt.u32.u64 %0, t; }" : "=r"(a) : "l"(p));
    return a;
}
__device__ __forceinline__ void cp_async16(uint32_t dst, const void* src) {
    asm volatile("cp.async.cg.shared.global [%0], [%1], 16;" :: "r"(dst), "l"(src) : "memory");
}
__device__ __forceinline__ void cp_async_commit() { asm volatile("cp.async.commit_group;" ::: "memory"); }
__device__ __forceinline__ void cp_async_wait1()  { asm volatile("cp.async.wait_group 1;" ::: "memory"); }
__device__ __forceinline__ void cp_async_wait0()  { asm volatile("cp.async.wait_group 0;" ::: "memory"); }

__device__ __forceinline__ void ldmatrix_x4(uint32_t* r, uint32_t addr) {
    asm volatile("ldmatrix.sync.aligned.m8n8.x4.shared.b16 {%0,%1,%2,%3}, [%4];"
                 : "=r"(r[0]), "=r"(r[1]), "=r"(r[2]), "=r"(r[3]) : "r"(addr));
}
__device__ __forceinline__ void mma_bf16(float* d, const uint32_t* a, uint32_t b0, uint32_t b1) {
    asm volatile("mma.sync.aligned.m16n8k16.row.col.f32.bf16.bf16.f32 "
                 "{%0,%1,%2,%3}, {%4,%5,%6,%7}, {%8,%9}, {%0,%1,%2,%3};"
                 : "+f"(d[0]), "+f"(d[1]), "+f"(d[2]), "+f"(d[3])
                 : "r"(a[0]), "r"(a[1]), "r"(a[2]), "r"(a[3]), "r"(b0), "r"(b1));
}

// ---------------- kernel: degree histogram + W transpose + coverage flags ----------------
// blocks [0,256): degree histogram; [256,1408): W transpose; [1408,1424): e2t coverage flags
__global__ void degree_prep_k(const int* __restrict__ eie, const int* __restrict__ ein,
                              const float* __restrict__ We, const float* __restrict__ Wn,
                              const int* __restrict__ t2e_out /* = e2t scatter map */) {
    int b = blockIdx.x;
    if (b < 256) {
        int idx = b * 1024 + threadIdx.x;
        int p = idx >> 15, e = idx & (EG - 1);
        int s = p >> 1, g = p & 1;
        const int* ei = (g ? ein : eie) + (size_t)s * 2 * EG;
        atomicAdd(&g_deg[p][ei[EG + e]], 1);
    } else if (b < 1408) {
        __shared__ float tile[32][33];
        int bx = b - 256;
        int z = bx / 576;
        int r = bx % 576;
        int gx = (r % 24) * 32, gy = (r / 24) * 32;
        int x = threadIdx.x & 31, y = threadIdx.x >> 5;
        const float* W = z ? Wn : We;
        __nv_bfloat16* o = g_Wt[z];
        tile[y][x] = W[(size_t)(gy + y) * DDIM + gx + x];
        __syncthreads();
        o[(size_t)(gx + y) * DDIM + gy + x] = __float2bfloat16(tile[x][y]);
    } else {
        int idx = (b - 1408) * 1024 + threadIdx.x;   // 16 blocks x 1024 = 16384
        int s = idx >> 12, i = idx & (NSUB - 1);
        g_flag[s][t2e_out[s * NSUB + i]] = 1;
    }
}

// ---------------- kernel: dinv + exclusive scan (one block per pair) ----------------
__global__ void scan_k() {
    int p = blockIdx.x;
    __shared__ int part[1024];
    int t = threadIdx.x;
    int base = t * 4;
    int a0 = g_deg[p][base + 0], a1 = g_deg[p][base + 1];
    int a2 = g_deg[p][base + 2], a3 = g_deg[p][base + 3];
    g_dinv[p][base + 0] = rsqrtf((float)(a0 + 1));
    g_dinv[p][base + 1] = rsqrtf((float)(a1 + 1));
    g_dinv[p][base + 2] = rsqrtf((float)(a2 + 1));
    g_dinv[p][base + 3] = rsqrtf((float)(a3 + 1));
    int s01 = a0 + a1, s012 = s01 + a2, s = s012 + a3;
    part[t] = s;
    __syncthreads();
    for (int off = 1; off < 1024; off <<= 1) {
        int v = (t >= off) ? part[t - off] : 0;
        __syncthreads();
        part[t] += v;
        __syncthreads();
    }
    int excl = part[t] - s;
    g_off[p][base + 0] = excl;        g_cur[p][base + 0] = excl;
    g_off[p][base + 1] = excl + a0;   g_cur[p][base + 1] = excl + a0;
    g_off[p][base + 2] = excl + s01;  g_cur[p][base + 2] = excl + s01;
    g_off[p][base + 3] = excl + s012; g_cur[p][base + 3] = excl + s012;
    if (t == 1023) g_off[p][NSUB] = part[1023];
}

// ---------------- kernel: CSR fill with precomputed (token, weight) payload ----------------
__global__ void fill_k(const int* __restrict__ eie, const int* __restrict__ ein,
                       const int* __restrict__ t2e, const int* __restrict__ t2n) {
    int idx = blockIdx.x * blockDim.x + threadIdx.x;
    int p = idx >> 15, e = idx & (EG - 1);
    int s = p >> 1, g = p & 1;
    const int* ei = (g ? ein : eie) + (size_t)s * 2 * EG;
    const int* map = (g ? t2n : t2e) + s * NSUB;
    int src = ei[e], dst = ei[EG + e];
    int pos = atomicAdd(&g_cur[p][dst], 1);
    g_ctok[p][pos] = map[src];
    g_cw [p][pos] = g_dinv[p][src];
}

// ---------------- kernel: sparse aggregation (z=0) + complement-only seed copy (z=1) ----------------
__global__ void agg_copy_k(const float* __restrict__ t,
                           const int* __restrict__ t2e, const int* __restrict__ t2n,
                           float* __restrict__ out) {
    if (blockIdx.z == 1) {
        // copy out=t only for tokens NOT covered by e2t (gemm graph-0 epilogue seeds the rest)
        int y = blockIdx.y;               // 8 chunks: sample = y>>1, row half = y&1
        int s = y >> 1;
        int row = ((y & 1) << 12) + blockIdx.x;
        if (g_flag[s][row]) return;
        size_t base = ((size_t)s * SDIM + row) * DDIM;
        ((float4*)(out + base))[threadIdx.x] = ((const float4*)(t + base))[threadIdx.x];
        return;
    }
    int p = blockIdx.y, dst = blockIdx.x;
    int s = p >> 1, g = p & 1;
    const int* map = (g ? t2n : t2e) + s * NSUB;
    const float* tb = t + (size_t)s * SDIM * DDIM;
    float dd = g_dinv[p][dst];
    int c = threadIdx.x;                     // 192 threads x float4 = 768
    const float4* row = (const float4*)(tb + (size_t)map[dst] * DDIM);
    float4 v = row[c];
    float w0 = dd * dd;
    float ax = w0 * v.x, ay = w0 * v.y, az = w0 * v.z, aw = w0 * v.w;
    int beg = g_off[p][dst], end = g_off[p][dst + 1];
    for (int e = beg; e < end; e++) {
        int tok = g_ctok[p][e];              // broadcast load
        float ws = dd * g_cw[p][e];          // broadcast load
        const float4* r2 = (const float4*)(tb + (size_t)tok * DDIM);
        float4 u = r2[c];
        ax += ws * u.x; ay += ws * u.y; az += ws * u.z; aw += ws * u.w;
    }
    __nv_bfloat162 h0, h1;
    h0.x = __float2bfloat16(ax); h0.y = __float2bfloat16(ay);
    h1.x = __float2bfloat16(az); h1.y = __float2bfloat16(aw);
    uint2 pk;
    pk.x = *(uint32_t*)&h0; pk.y = *(uint32_t*)&h1;
    *(uint2*)(&g_agg[g][((size_t)(s * NSUB + dst)) * DDIM + c * 4]) = pk;
}

// ---------------- kernel: per-graph GEMM (r7 core) + fused epilogue ----------------
// graph 0: out[tok] = t[tok] + gt*(C+bias)   (non-atomic seed write, covers e2t rows)
// graph 1: out[tok] += gt*(C+bias)           (atomicAdd; out fully seeded by then)
// CTA tile 128x128, 4 warps (2 warpM x 2 warpN), warp tile 64x64, K chunk 32, 3 smem stages.
#define KT 24                // 768 / 32
#define ROWB 80              // padded SMEM row bytes -> conflict-free ldmatrix
#define STAGE_B (128 * ROWB) // 10240 bytes per operand per stage
__global__ void __launch_bounds__(128, 2) gemm_k(int graph,
        const float* __restrict__ bias, const float* __restrict__ gate,
        const int* __restrict__ smap, const float* __restrict__ tsrc,
        float* __restrict__ out)
{
    extern __shared__ __align__(16) char dsm[];   // 3 * (10240 + 10240) = 61440
    const char* A  = (const char*)g_agg[graph];
    const char* Bw = (const char*)g_Wt[graph];

    int tid = threadIdx.x, lane = tid & 31, wid = tid >> 5;
    int warpM = wid >> 1, warpN = wid & 1;    // 2x2 warps, warp tile 64x64
    int ntile = blockIdx.x, mtile = blockIdx.y;

    const char* abase = A  + (size_t)(mtile * 128) * (DDIM * 2);
    const char* bbase = Bw + (size_t)(ntile * 128) * (DDIM * 2);
    uint32_t smbase = smem_u32(dsm);

    float acc[4][8][4];
    #pragma unroll
    for (int i = 0; i < 4; i++)
        #pragma unroll
        for (int j = 0; j < 8; j++)
            #pragma unroll
            for (int r = 0; r < 4; r++) acc[i][j][r] = 0.f;

    auto load_tile = [&](int buf, int kt) {
        uint32_t dA = smbase + buf * (2 * STAGE_B);
        uint32_t dB = dA + STAGE_B;
        #pragma unroll
        for (int i = 0; i < 4; i++) {
            int ci = i * 128 + tid;
            int r = ci >> 2, c = ci & 3;
            cp_async16(dA + r * ROWB + c * 16, abase + (size_t)r * (DDIM * 2) + kt * 64 + c * 16);
            cp_async16(dB + r * ROWB + c * 16, bbase + (size_t)r * (DDIM * 2) + kt * 64 + c * 16);
        }
        cp_async_commit();
    };

    load_tile(0, 0);
    load_tile(1, 1);

    int grp = lane >> 3, lr = lane & 7;
    for (int kt = 0; kt < KT; kt++) {
        if (kt < KT - 1) cp_async_wait1();
        else             cp_async_wait0();
        __syncthreads();
        if (kt + 2 < KT) load_tile((kt + 2) % 3, kt + 2);   // overwrites stage (kt-1)%3: safe

        int buf = kt % 3;
        uint32_t baseA = smbase + buf * (2 * STAGE_B);
        uint32_t baseB = baseA + STAGE_B;
        #pragma unroll
        for (int ka = 0; ka < 2; ka++) {
            int chunk = ka * 2 + (grp >> 1);
            uint32_t af[4][4];
            #pragma unroll
            for (int am = 0; am < 4; am++) {
                int row = warpM * 64 + am * 16 + (grp & 1) * 8 + lr;
                ldmatrix_x4(af[am], baseA + row * ROWB + chunk * 16);
            }
            uint32_t bf[4][4];
            #pragma unroll
            for (int p = 0; p < 4; p++) {
                int nrow = warpN * 64 + p * 16 + (grp & 1) * 8 + lr;
                ldmatrix_x4(bf[p], baseB + nrow * ROWB + chunk * 16);
            }
            // b-frag pairing: b0={n,k0-7}=r[an&1], b1={n,k8-15}=r[(an&1)+2]
            #pragma unroll
            for (int am = 0; am < 4; am++)
                #pragma unroll
                for (int an = 0; an < 8; an++)
                    mma_bf16(acc[am][an], af[am], bf[an >> 1][an & 1], bf[an >> 1][(an & 1) + 2]);
        }
    }

    float gt = tanhf(gate[0]);
    int ncol0 = ntile * 128 + warpN * 64;
    #pragma unroll
    for (int am = 0; am < 4; am++) {
        #pragma unroll
        for (int half = 0; half < 2; half++) {
            int row = mtile * 128 + warpM * 64 + am * 16 + (lane >> 2) + half * 8;
            int s = row >> 12, i = row & (NSUB - 1);
            int tok = smap[s * NSUB + i];
            size_t base = ((size_t)s * SDIM + tok) * DDIM + ncol0;
            if (graph == 0) {
                // seed write: out = t + gt*(C + bias); unique (tok,col) per thread in launch
                #pragma unroll
                for (int an = 0; an < 8; an++) {
                    int n = an * 8 + (lane & 3) * 2;
                    float2 tv = *(const float2*)(tsrc + base + n);
                    float2 o;
                    o.x = tv.x + gt * (acc[am][an][half * 2 + 0] + bias[ncol0 + n + 0]);
                    o.y = tv.y + gt * (acc[am][an][half * 2 + 1] + bias[ncol0 + n + 1]);
                    *(float2*)(out + base + n) = o;
                }
            } else {
                #pragma unroll
                for (int an = 0; an < 8; an++) {
                    int n = an * 8 + (lane & 3) * 2;
                    atomicAdd(out + base + n + 0, gt * (acc[am][an][half * 2 + 0] + bias[ncol0 + n + 0]));
                    atomicAdd(out + base + n + 1, gt * (acc[am][an][half * 2 + 1] + bias[ncol0 + n + 1]));
                }
            }
        }
    }
}

// ---------------- launch ----------------
extern "C" void kernel_launch(void* const* d_in, const int* in_sizes, int n_in,
                              void* d_out, int out_size) {
    const float* t   = (const float*)d_in[0];
    const int*   t2e = (const int*)d_in[1];
    const int*   e2t = (const int*)d_in[2];
    const int*   t2n = (const int*)d_in[3];
    const int*   n2t = (const int*)d_in[4];
    const int*   eie = (const int*)d_in[5];
    const int*   ein = (const int*)d_in[6];
    const float* We  = (const float*)d_in[7];
    const float* be  = (const float*)d_in[8];
    const float* Wn  = (const float*)d_in[9];
    const float* bn  = (const float*)d_in[10];
    const float* ga  = (const float*)d_in[11];
    const float* gb  = (const float*)d_in[12];
    float* out = (float*)d_out;

    void* addr = nullptr;
    cudaGetSymbolAddress(&addr, g_deg);
    cudaMemsetAsync(addr, 0, sizeof(int) * NPAIR * NSUB);
    cudaGetSymbolAddress(&addr, g_flag);
    cudaMemsetAsync(addr, 0, (size_t)BDIM * SDIM);

    degree_prep_k<<<256 + 1152 + 16, 1024>>>(eie, ein, We, Wn, e2t);
    scan_k<<<NPAIR, 1024>>>();
    fill_k<<<(NPAIR * EG) / 1024, 1024>>>(eie, ein, t2e, t2n);
    agg_copy_k<<<dim3(NSUB, NPAIR, 2), 192>>>(t, t2e, t2n, out);

    cudaFuncSetAttribute(gemm_k, cudaFuncAttributeMaxDynamicSharedMemorySize, 3 * 2 * STAGE_B);
    gemm_k<<<dim3(DDIM / 128, (BDIM * NSUB) / 128), 128, 3 * 2 * STAGE_B>>>(
        0, be, ga, e2t, t, out);
    gemm_k<<<dim3(DDIM / 128, (BDIM * NSUB) / 128), 128, 3 * 2 * STAGE_B>>>(
        1, bn, gb, n2t, t, out);
}

// round 10
// speedup vs baseline: 1.0483x; 1.0483x over previous
#include <cuda_runtime.h>
#include <cuda_bf16.h>
#include <cstdint>
#include <cstddef>

#define BDIM 4
#define SDIM 8192
#define DDIM 768
#define NSUB 4096
#define EG   32768
#define NPAIR 8   // p = sample*2 + graph (graph 0 = edges, 1 = nodes)

// ---------------- static device scratch ----------------
__device__ int   g_deg [NPAIR][NSUB];
__device__ int   g_off [NPAIR][NSUB + 1];
__device__ int   g_cur [NPAIR][NSUB];
__device__ float g_dinv[NPAIR][NSUB];
__device__ int   g_csr [NPAIR][EG + 1];   // +1: prefetch overread pad
__device__ __align__(16) __nv_bfloat16 g_agg[2][(size_t)BDIM * NSUB * DDIM];
__device__ __align__(16) __nv_bfloat16 g_Wt [2][DDIM * DDIM];   // W^T bf16: [n][k]

// ---------------- PTX helpers (sm_80-era features only) ----------------
__device__ __forceinline__ uint32_t smem_u32(const void* p) {
    uint32_t a;
    asm("{ .reg .u64 t; cvta.to.shared.u64 t, %1; cvt.u32.u64 %0, t; }" : "=r"(a) : "l"(p));
    return a;
}
__device__ __forceinline__ void cp_async16(uint32_t dst, const void* src) {
    asm volatile("cp.async.cg.shared.global [%0], [%1], 16;" :: "r"(dst), "l"(src) : "memory");
}
__device__ __forceinline__ void cp_async_commit() { asm volatile("cp.async.commit_group;" ::: "memory"); }
__device__ __forceinline__ void cp_async_wait1()  { asm volatile("cp.async.wait_group 1;" ::: "memory"); }
__device__ __forceinline__ void cp_async_wait0()  { asm volatile("cp.async.wait_group 0;" ::: "memory"); }

__device__ __forceinline__ void ldmatrix_x4(uint32_t* r, uint32_t addr) {
    asm volatile("ldmatrix.sync.aligned.m8n8.x4.shared.b16 {%0,%1,%2,%3}, [%4];"
                 : "=r"(r[0]), "=r"(r[1]), "=r"(r[2]), "=r"(r[3]) : "r"(addr));
}
__device__ __forceinline__ void mma_bf16(float* d, const uint32_t* a, uint32_t b0, uint32_t b1) {
    asm volatile("mma.sync.aligned.m16n8k16.row.col.f32.bf16.bf16.f32 "
                 "{%0,%1,%2,%3}, {%4,%5,%6,%7}, {%8,%9}, {%0,%1,%2,%3};"
                 : "+f"(d[0]), "+f"(d[1]), "+f"(d[2]), "+f"(d[3])
                 : "r"(a[0]), "r"(a[1]), "r"(a[2]), "r"(a[3]), "r"(b0), "r"(b1));
}

// ---------------- kernel: degree histogram + W transpose (fused, disjoint block ranges) ----------------
__global__ void degree_prep_k(const int* __restrict__ eie, const int* __restrict__ ein,
                              const float* __restrict__ We, const float* __restrict__ Wn) {
    int b = blockIdx.x;
    if (b < 256) {
        int idx = b * 1024 + threadIdx.x;
        int p = idx >> 15, e = idx & (EG - 1);
        int s = p >> 1, g = p & 1;
        const int* ei = (g ? ein : eie) + (size_t)s * 2 * EG;
        atomicAdd(&g_deg[p][ei[EG + e]], 1);
    } else {
        __shared__ float tile[32][33];
        int bx = b - 256;
        int z = bx / 576;
        int r = bx % 576;
        int gx = (r % 24) * 32, gy = (r / 24) * 32;
        int x = threadIdx.x & 31, y = threadIdx.x >> 5;
        const float* W = z ? Wn : We;
        __nv_bfloat16* o = g_Wt[z];
        tile[y][x] = W[(size_t)(gy + y) * DDIM + gx + x];
        __syncthreads();
        o[(size_t)(gx + y) * DDIM + gy + x] = __float2bfloat16(tile[x][y]);
    }
}

// ---------------- kernel: dinv + exclusive scan (one block per pair) ----------------
__global__ void scan_k() {
    int p = blockIdx.x;
    __shared__ int part[1024];
    int t = threadIdx.x;
    int base = t * 4;
    int a0 = g_deg[p][base + 0], a1 = g_deg[p][base + 1];
    int a2 = g_deg[p][base + 2], a3 = g_deg[p][base + 3];
    g_dinv[p][base + 0] = rsqrtf((float)(a0 + 1));
    g_dinv[p][base + 1] = rsqrtf((float)(a1 + 1));
    g_dinv[p][base + 2] = rsqrtf((float)(a2 + 1));
    g_dinv[p][base + 3] = rsqrtf((float)(a3 + 1));
    int s01 = a0 + a1, s012 = s01 + a2, s = s012 + a3;
    part[t] = s;
    __syncthreads();
    for (int off = 1; off < 1024; off <<= 1) {
        int v = (t >= off) ? part[t - off] : 0;
        __syncthreads();
        part[t] += v;
        __syncthreads();
    }
    int excl = part[t] - s;
    g_off[p][base + 0] = excl;        g_cur[p][base + 0] = excl;
    g_off[p][base + 1] = excl + a0;   g_cur[p][base + 1] = excl + a0;
    g_off[p][base + 2] = excl + s01;  g_cur[p][base + 2] = excl + s01;
    g_off[p][base + 3] = excl + s012; g_cur[p][base + 3] = excl + s012;
    if (t == 1023) g_off[p][NSUB] = part[1023];
}

// ---------------- kernel: CSR fill ----------------
__global__ void fill_k(const int* __restrict__ eie, const int* __restrict__ ein) {
    int idx = blockIdx.x * blockDim.x + threadIdx.x;
    int p = idx >> 15, e = idx & (EG - 1);
    int s = p >> 1, g = p & 1;
    const int* ei = (g ? ein : eie) + (size_t)s * 2 * EG;
    int src = ei[e], dst = ei[EG + e];
    int pos = atomicAdd(&g_cur[p][dst], 1);
    g_csr[p][pos] = src;
}

// ---------------- kernel: sparse aggregation (z=0,1 column halves) + seed copy (z=2,3) ----------------
// 96-thread blocks: doubles independent gather chains per SM vs 192-thread blocks,
// improving latency hiding (agg is dependency-latency-bound, no pipe saturated).
__global__ void agg_copy_k(const float* __restrict__ t,
                           const int* __restrict__ t2e, const int* __restrict__ t2n,
                           float* __restrict__ out) {
    int z = blockIdx.z;
    if (z >= 2) {
        // seed copy out = t : 2 z-slices x 8 x 4096 blocks x 96 threads x float4 = 100.7MB
        size_t i = (((size_t)(z - 2) * NPAIR * NSUB + (size_t)blockIdx.y * NSUB + blockIdx.x) * 96
                    + threadIdx.x);
        ((float4*)out)[i] = ((const float4*)t)[i];
        return;
    }
    int p = blockIdx.y, dst = blockIdx.x;
    int s = p >> 1, g = p & 1;
    const int* map = (g ? t2n : t2e) + s * NSUB;
    const float* tb = t + (size_t)s * SDIM * DDIM;
    float dd = g_dinv[p][dst];
    int cc = z * 96 + threadIdx.x;           // float4 index 0..191 (columns cc*4..cc*4+3)
    const float4* row = (const float4*)(tb + (size_t)map[dst] * DDIM);
    float4 v = row[cc];
    float w0 = dd * dd;
    float ax = w0 * v.x, ay = w0 * v.y, az = w0 * v.z, aw = w0 * v.w;
    int beg = g_off[p][dst], end = g_off[p][dst + 1];
    int src = g_csr[p][beg];                 // prefetch (padded array: safe even if beg==end)
    for (int e = beg; e < end; e++) {
        int nsrc = g_csr[p][e + 1];          // next-iteration prefetch
        float ws = dd * g_dinv[p][src];
        const float4* r2 = (const float4*)(tb + (size_t)map[src] * DDIM);
        float4 u = r2[cc];
        ax += ws * u.x; ay += ws * u.y; az += ws * u.z; aw += ws * u.w;
        src = nsrc;
    }
    __nv_bfloat162 h0, h1;
    h0.x = __float2bfloat16(ax); h0.y = __float2bfloat16(ay);
    h1.x = __float2bfloat16(az); h1.y = __float2bfloat16(aw);
    uint2 pk;
    pk.x = *(uint32_t*)&h0; pk.y = *(uint32_t*)&h1;
    *(uint2*)(&g_agg[g][((size_t)(s * NSUB + dst)) * DDIM + cc * 4]) = pk;
}

// ---------------- kernel: both GEMMs fused, wide warp tile, atomic epilogue (round-7 core) ----------------
// z = graph. C[16384,768] = agg @ W ; out[s, smap[i], :] += tanh(gate) * (C + bias)
// CTA tile 128x128, 4 warps (2 warpM x 2 warpN), warp tile 64x64, K chunk 32, 3 smem stages.
#define KT 24                // 768 / 32
#define ROWB 80              // padded SMEM row bytes -> conflict-free ldmatrix
#define STAGE_B (128 * ROWB) // 10240 bytes per operand per stage
__global__ void __launch_bounds__(128, 2) gemm_k(
        const float* __restrict__ be, const float* __restrict__ bn,
        const float* __restrict__ ga, const float* __restrict__ gb,
        const int* __restrict__ e2t, const int* __restrict__ n2t,
        float* __restrict__ out)
{
    extern __shared__ __align__(16) char dsm[];   // 3 * (10240 + 10240) = 61440
    int graph = blockIdx.z;
    const float* bias = graph ? bn : be;
    const float* gate = graph ? gb : ga;
    const int*   smap = graph ? n2t : e2t;
    const char* A  = (const char*)g_agg[graph];
    const char* Bw = (const char*)g_Wt[graph];

    int tid = threadIdx.x, lane = tid & 31, wid = tid >> 5;
    int warpM = wid >> 1, warpN = wid & 1;    // 2x2 warps, warp tile 64x64
    int ntile = blockIdx.x, mtile = blockIdx.y;

    const char* abase = A  + (size_t)(mtile * 128) * (DDIM * 2);
    const char* bbase = Bw + (size_t)(ntile * 128) * (DDIM * 2);
    uint32_t smbase = smem_u32(dsm);

    float acc[4][8][4];
    #pragma unroll
    for (int i = 0; i < 4; i++)
        #pragma unroll
        for (int j = 0; j < 8; j++)
            #pragma unroll
            for (int r = 0; r < 4; r++) acc[i][j][r] = 0.f;

    auto load_tile = [&](int buf, int kt) {
        uint32_t dA = smbase + buf * (2 * STAGE_B);
        uint32_t dB = dA + STAGE_B;
        #pragma unroll
        for (int i = 0; i < 4; i++) {
            int ci = i * 128 + tid;
            int r = ci >> 2, c = ci & 3;
            cp_async16(dA + r * ROWB + c * 16, abase + (size_t)r * (DDIM * 2) + kt * 64 + c * 16);
            cp_async16(dB + r * ROWB + c * 16, bbase + (size_t)r * (DDIM * 2) + kt * 64 + c * 16);
        }
        cp_async_commit();
    };

    load_tile(0, 0);
    load_tile(1, 1);

    int grp = lane >> 3, lr = lane & 7;
    for (int kt = 0; kt < KT; kt++) {
        if (kt < KT - 1) cp_async_wait1();
        else             cp_async_wait0();
        __syncthreads();
        if (kt + 2 < KT) load_tile((kt + 2) % 3, kt + 2);   // overwrites stage (kt-1)%3: safe

        int buf = kt % 3;
        uint32_t baseA = smbase + buf * (2 * STAGE_B);
        uint32_t baseB = baseA + STAGE_B;
        #pragma unroll
        for (int ka = 0; ka < 2; ka++) {
            int chunk = ka * 2 + (grp >> 1);
            uint32_t af[4][4];
            #pragma unroll
            for (int am = 0; am < 4; am++) {
                int row = warpM * 64 + am * 16 + (grp & 1) * 8 + lr;
                ldmatrix_x4(af[am], baseA + row * ROWB + chunk * 16);
            }
            uint32_t bf[4][4];
            #pragma unroll
            for (int p = 0; p < 4; p++) {
                int nrow = warpN * 64 + p * 16 + (grp & 1) * 8 + lr;
                ldmatrix_x4(bf[p], baseB + nrow * ROWB + chunk * 16);
            }
            // b-frag pairing: b0={n,k0-7}=r[an&1], b1={n,k8-15}=r[(an&1)+2]
            #pragma unroll
            for (int am = 0; am < 4; am++)
                #pragma unroll
                for (int an = 0; an < 8; an++)
                    mma_bf16(acc[am][an], af[am], bf[an >> 1][an & 1], bf[an >> 1][(an & 1) + 2]);
        }
    }

    // epilogue: fused bias + tanh(gate), scatter via atomic add
    // (atomics required: both graphs run concurrently in this launch and may hit the same token)
    float gt = tanhf(gate[0]);
    int ncol0 = ntile * 128 + warpN * 64;
    #pragma unroll
    for (int am = 0; am < 4; am++) {
        #pragma unroll
        for (int half = 0; half < 2; half++) {
            int row = mtile * 128 + warpM * 64 + am * 16 + (lane >> 2) + half * 8;
            int s = row >> 12, i = row & (NSUB - 1);
            int tok = smap[s * NSUB + i];
            float* orow = out + ((size_t)s * SDIM + tok) * DDIM + ncol0;
            #pragma unroll
            for (int an = 0; an < 8; an++) {
                int n = an * 8 + (lane & 3) * 2;
                atomicAdd(orow + n + 0, gt * (acc[am][an][half * 2 + 0] + bias[ncol0 + n + 0]));
                atomicAdd(orow + n + 1, gt * (acc[am][an][half * 2 + 1] + bias[ncol0 + n + 1]));
            }
        }
    }
}

// ---------------- launch ----------------
extern "C" void kernel_launch(void* const* d_in, const int* in_sizes, int n_in,
                              void* d_out, int out_size) {
    const float* t   = (const float*)d_in[0];
    const int*   t2e = (const int*)d_in[1];
    const int*   e2t = (const int*)d_in[2];
    const int*   t2n = (const int*)d_in[3];
    const int*   n2t = (const int*)d_in[4];
    const int*   eie = (const int*)d_in[5];
    const int*   ein = (const int*)d_in[6];
    const float* We  = (const float*)d_in[7];
    const float* be  = (const float*)d_in[8];
    const float* Wn  = (const float*)d_in[9];
    const float* bn  = (const float*)d_in[10];
    const float* ga  = (const float*)d_in[11];
    const float* gb  = (const float*)d_in[12];
    float* out = (float*)d_out;

    void* degAddr = nullptr;
    cudaGetSymbolAddress(&degAddr, g_deg);
    cudaMemsetAsync(degAddr, 0, sizeof(int) * NPAIR * NSUB);

    degree_prep_k<<<256 + 1152, 1024>>>(eie, ein, We, Wn);
    scan_k<<<NPAIR, 1024>>>();
    fill_k<<<(NPAIR * EG) / 1024, 1024>>>(eie, ein);
    agg_copy_k<<<dim3(NSUB, NPAIR, 4), 96>>>(t, t2e, t2n, out);

    cudaFuncSetAttribute(gemm_k, cudaFuncAttributeMaxDynamicSharedMemorySize, 3 * 2 * STAGE_B);
    gemm_k<<<dim3(DDIM / 128, (BDIM * NSUB) / 128, 2), 128, 3 * 2 * STAGE_B>>>(
        be, bn, ga, gb, e2t, n2t, out);
}

// round 11
// speedup vs baseline: 1.1245x; 1.0726x over previous
#include <cuda_runtime.h>
#include <cuda_bf16.h>
#include <cstdint>
#include <cstddef>

#define BDIM 4
#define SDIM 8192
#define DDIM 768
#define NSUB 4096
#define EG   32768
#define NPAIR 8   // p = sample*2 + graph (graph 0 = edges, 1 = nodes)

// ---------------- static device scratch ----------------
// g_deg is zero at module load; scan_k re-zeroes it after reading, so every
// kernel_launch call (and every graph replay) sees zeros deterministically.
__device__ int   g_deg [NPAIR][NSUB];
__device__ int   g_off [NPAIR][NSUB + 1];
__device__ int   g_cur [NPAIR][NSUB];
__device__ float g_dinv[NPAIR][NSUB];
__device__ int   g_csr [NPAIR][EG];
__device__ __align__(16) __nv_bfloat16 g_agg[2][(size_t)BDIM * NSUB * DDIM];
__device__ __align__(16) __nv_bfloat16 g_Wt [2][DDIM * DDIM];   // W^T bf16: [n][k]

// ---------------- PTX helpers (sm_80/sm_90 features only) ----------------
__device__ __forceinline__ uint32_t smem_u32(const void* p) {
    uint32_t a;
    asm("{ .reg .u64 t; cvta.to.shared.u64 t, %1; cvt.u32.u64 %0, t; }" : "=r"(a) : "l"(p));
    return a;
}
__device__ __forceinline__ void cp_async16(uint32_t dst, const void* src) {
    asm volatile("cp.async.cg.shared.global [%0], [%1], 16;" :: "r"(dst), "l"(src) : "memory");
}
__device__ __forceinline__ void cp_async_commit() { asm volatile("cp.async.commit_group;" ::: "memory"); }
__device__ __forceinline__ void cp_async_wait1()  { asm volatile("cp.async.wait_group 1;" ::: "memory"); }
__device__ __forceinline__ void cp_async_wait0()  { asm volatile("cp.async.wait_group 0;" ::: "memory"); }

__device__ __forceinline__ void ldmatrix_x4(uint32_t* r, uint32_t addr) {
    asm volatile("ldmatrix.sync.aligned.m8n8.x4.shared.b16 {%0,%1,%2,%3}, [%4];"
                 : "=r"(r[0]), "=r"(r[1]), "=r"(r[2]), "=r"(r[3]) : "r"(addr));
}
__device__ __forceinline__ void mma_bf16(float* d, const uint32_t* a, uint32_t b0, uint32_t b1) {
    asm volatile("mma.sync.aligned.m16n8k16.row.col.f32.bf16.bf16.f32 "
                 "{%0,%1,%2,%3}, {%4,%5,%6,%7}, {%8,%9}, {%0,%1,%2,%3};"
                 : "+f"(d[0]), "+f"(d[1]), "+f"(d[2]), "+f"(d[3])
                 : "r"(a[0]), "r"(a[1]), "r"(a[2]), "r"(a[3]), "r"(b0), "r"(b1));
}
// vectorized global reduction (PTX ISA 8.1+, sm_90+): one REDG for two floats
__device__ __forceinline__ void red_add_v2(float* ptr, float a, float b) {
    asm volatile("red.global.add.v2.f32 [%0], {%1, %2};" :: "l"(ptr), "f"(a), "f"(b) : "memory");
}

// ---------------- kernel: degree histogram + W transpose (fused, disjoint block ranges) ----------------
__global__ void degree_prep_k(const int* __restrict__ eie, const int* __restrict__ ein,
                              const float* __restrict__ We, const float* __restrict__ Wn) {
    int b = blockIdx.x;
    if (b < 256) {
        int idx = b * 1024 + threadIdx.x;
        int p = idx >> 15, e = idx & (EG - 1);
        int s = p >> 1, g = p & 1;
        const int* ei = (g ? ein : eie) + (size_t)s * 2 * EG;
        atomicAdd(&g_deg[p][ei[EG + e]], 1);
    } else {
        __shared__ float tile[32][33];
        int bx = b - 256;
        int z = bx / 576;
        int r = bx % 576;
        int gx = (r % 24) * 32, gy = (r / 24) * 32;
        int x = threadIdx.x & 31, y = threadIdx.x >> 5;
        const float* W = z ? Wn : We;
        __nv_bfloat16* o = g_Wt[z];
        tile[y][x] = W[(size_t)(gy + y) * DDIM + gx + x];
        __syncthreads();
        o[(size_t)(gx + y) * DDIM + gy + x] = __float2bfloat16(tile[x][y]);
    }
}

// ---------------- kernel: dinv + exclusive scan; re-zeroes g_deg for the next call ----------------
__global__ void scan_k() {
    int p = blockIdx.x;
    __shared__ int part[1024];
    int t = threadIdx.x;
    int base = t * 4;
    int a0 = g_deg[p][base + 0], a1 = g_deg[p][base + 1];
    int a2 = g_deg[p][base + 2], a3 = g_deg[p][base + 3];
    g_deg[p][base + 0] = 0; g_deg[p][base + 1] = 0;   // leave zeroed for next launch/replay
    g_deg[p][base + 2] = 0; g_deg[p][base + 3] = 0;
    g_dinv[p][base + 0] = rsqrtf((float)(a0 + 1));
    g_dinv[p][base + 1] = rsqrtf((float)(a1 + 1));
    g_dinv[p][base + 2] = rsqrtf((float)(a2 + 1));
    g_dinv[p][base + 3] = rsqrtf((float)(a3 + 1));
    int s01 = a0 + a1, s012 = s01 + a2, s = s012 + a3;
    part[t] = s;
    __syncthreads();
    for (int off = 1; off < 1024; off <<= 1) {
        int v = (t >= off) ? part[t - off] : 0;
        __syncthreads();
        part[t] += v;
        __syncthreads();
    }
    int excl = part[t] - s;
    g_off[p][base + 0] = excl;        g_cur[p][base + 0] = excl;
    g_off[p][base + 1] = excl + a0;   g_cur[p][base + 1] = excl + a0;
    g_off[p][base + 2] = excl + s01;  g_cur[p][base + 2] = excl + s01;
    g_off[p][base + 3] = excl + s012; g_cur[p][base + 3] = excl + s012;
    if (t == 1023) g_off[p][NSUB] = part[1023];
}

// ---------------- kernel: CSR fill ----------------
__global__ void fill_k(const int* __restrict__ eie, const int* __restrict__ ein) {
    int idx = blockIdx.x * blockDim.x + threadIdx.x;
    int p = idx >> 15, e = idx & (EG - 1);
    int s = p >> 1, g = p & 1;
    const int* ei = (g ? ein : eie) + (size_t)s * 2 * EG;
    int src = ei[e], dst = ei[EG + e];
    int pos = atomicAdd(&g_cur[p][dst], 1);
    g_csr[p][pos] = src;
}

// ---------------- kernel: sparse aggregation (z=0) + seed copy out=t (z=1) ----------------
// round-7 form: 192 threads, simple loop, 32 regs, occ ~84% — empirically optimal
__global__ void agg_copy_k(const float* __restrict__ t,
                           const int* __restrict__ t2e, const int* __restrict__ t2n,
                           float* __restrict__ out) {
    if (blockIdx.z == 1) {
        size_t i = (((size_t)blockIdx.y * NSUB + blockIdx.x) * 192 + threadIdx.x);
        ((float4*)out)[i] = ((const float4*)t)[i];
        return;
    }
    int p = blockIdx.y, dst = blockIdx.x;
    int s = p >> 1, g = p & 1;
    const int* map = (g ? t2n : t2e) + s * NSUB;
    const float* tb = t + (size_t)s * SDIM * DDIM;
    float dd = g_dinv[p][dst];
    int c = threadIdx.x;                     // 192 threads x float4 = 768
    const float4* row = (const float4*)(tb + (size_t)map[dst] * DDIM);
    float4 v = row[c];
    float w0 = dd * dd;
    float ax = w0 * v.x, ay = w0 * v.y, az = w0 * v.z, aw = w0 * v.w;
    int beg = g_off[p][dst], end = g_off[p][dst + 1];
    for (int e = beg; e < end; e++) {
        int src = g_csr[p][e];
        float ws = dd * g_dinv[p][src];
        const float4* r2 = (const float4*)(tb + (size_t)map[src] * DDIM);
        float4 u = r2[c];
        ax += ws * u.x; ay += ws * u.y; az += ws * u.z; aw += ws * u.w;
    }
    __nv_bfloat162 h0, h1;
    h0.x = __float2bfloat16(ax); h0.y = __float2bfloat16(ay);
    h1.x = __float2bfloat16(az); h1.y = __float2bfloat16(aw);
    uint2 pk;
    pk.x = *(uint32_t*)&h0; pk.y = *(uint32_t*)&h1;
    *(uint2*)(&g_agg[g][((size_t)(s * NSUB + dst)) * DDIM + c * 4]) = pk;
}

// ---------------- kernel: both GEMMs fused, wide warp tile, v2-reduction epilogue ----------------
// z = graph. C[16384,768] = agg @ W ; out[s, smap[i], :] += tanh(gate) * (C + bias)
// CTA tile 128x128, 4 warps (2 warpM x 2 warpN), warp tile 64x64, K chunk 32, 3 smem stages.
#define KT 24                // 768 / 32
#define ROWB 80              // padded SMEM row bytes -> conflict-free ldmatrix
#define STAGE_B (128 * ROWB) // 10240 bytes per operand per stage
__global__ void __launch_bounds__(128, 2) gemm_k(
        const float* __restrict__ be, const float* __restrict__ bn,
        const float* __restrict__ ga, const float* __restrict__ gb,
        const int* __restrict__ e2t, const int* __restrict__ n2t,
        float* __restrict__ out)
{
    extern __shared__ __align__(16) char dsm[];   // 3 * (10240 + 10240) = 61440
    int graph = blockIdx.z;
    const float* bias = graph ? bn : be;
    const float* gate = graph ? gb : ga;
    const int*   smap = graph ? n2t : e2t;
    const char* A  = (const char*)g_agg[graph];
    const char* Bw = (const char*)g_Wt[graph];

    int tid = threadIdx.x, lane = tid & 31, wid = tid >> 5;
    int warpM = wid >> 1, warpN = wid & 1;    // 2x2 warps, warp tile 64x64
    int ntile = blockIdx.x, mtile = blockIdx.y;

    const char* abase = A  + (size_t)(mtile * 128) * (DDIM * 2);
    const char* bbase = Bw + (size_t)(ntile * 128) * (DDIM * 2);
    uint32_t smbase = smem_u32(dsm);

    float acc[4][8][4];
    #pragma unroll
    for (int i = 0; i < 4; i++)
        #pragma unroll
        for (int j = 0; j < 8; j++)
            #pragma unroll
            for (int r = 0; r < 4; r++) acc[i][j][r] = 0.f;

    auto load_tile = [&](int buf, int kt) {
        uint32_t dA = smbase + buf * (2 * STAGE_B);
        uint32_t dB = dA + STAGE_B;
        #pragma unroll
        for (int i = 0; i < 4; i++) {
            int ci = i * 128 + tid;
            int r = ci >> 2, c = ci & 3;
            cp_async16(dA + r * ROWB + c * 16, abase + (size_t)r * (DDIM * 2) + kt * 64 + c * 16);
            cp_async16(dB + r * ROWB + c * 16, bbase + (size_t)r * (DDIM * 2) + kt * 64 + c * 16);
        }
        cp_async_commit();
    };

    load_tile(0, 0);
    load_tile(1, 1);

    int grp = lane >> 3, lr = lane & 7;
    for (int kt = 0; kt < KT; kt++) {
        if (kt < KT - 1) cp_async_wait1();
        else             cp_async_wait0();
        __syncthreads();
        if (kt + 2 < KT) load_tile((kt + 2) % 3, kt + 2);   // overwrites stage (kt-1)%3: safe

        int buf = kt % 3;
        uint32_t baseA = smbase + buf * (2 * STAGE_B);
        uint32_t baseB = baseA + STAGE_B;
        #pragma unroll
        for (int ka = 0; ka < 2; ka++) {
            int chunk = ka * 2 + (grp >> 1);
            uint32_t af[4][4];
            #pragma unroll
            for (int am = 0; am < 4; am++) {
                int row = warpM * 64 + am * 16 + (grp & 1) * 8 + lr;
                ldmatrix_x4(af[am], baseA + row * ROWB + chunk * 16);
            }
            uint32_t bf[4][4];
            #pragma unroll
            for (int p = 0; p < 4; p++) {
                int nrow = warpN * 64 + p * 16 + (grp & 1) * 8 + lr;
                ldmatrix_x4(bf[p], baseB + nrow * ROWB + chunk * 16);
            }
            // b-frag pairing: b0={n,k0-7}=r[an&1], b1={n,k8-15}=r[(an&1)+2]
            #pragma unroll
            for (int am = 0; am < 4; am++)
                #pragma unroll
                for (int an = 0; an < 8; an++)
                    mma_bf16(acc[am][an], af[am], bf[an >> 1][an & 1], bf[an >> 1][(an & 1) + 2]);
        }
    }

    // epilogue: fused bias + tanh(gate), scatter via vectorized red.global.add.v2.f32
    // (reduction required: both graphs run concurrently in this launch and may hit the same token;
    //  v2 halves REDG instruction count vs scalar atomicAdd)
    float gt = tanhf(gate[0]);
    int ncol0 = ntile * 128 + warpN * 64;
    #pragma unroll
    for (int am = 0; am < 4; am++) {
        #pragma unroll
        for (int half = 0; half < 2; half++) {
            int row = mtile * 128 + warpM * 64 + am * 16 + (lane >> 2) + half * 8;
            int s = row >> 12, i = row & (NSUB - 1);
            int tok = smap[s * NSUB + i];
            float* orow = out + ((size_t)s * SDIM + tok) * DDIM + ncol0;
            #pragma unroll
            for (int an = 0; an < 8; an++) {
                int n = an * 8 + (lane & 3) * 2;   // 8B-aligned pair
                red_add_v2(orow + n,
                           gt * (acc[am][an][half * 2 + 0] + bias[ncol0 + n + 0]),
                           gt * (acc[am][an][half * 2 + 1] + bias[ncol0 + n + 1]));
            }
        }
    }
}

// ---------------- launch ----------------
extern "C" void kernel_launch(void* const* d_in, const int* in_sizes, int n_in,
                              void* d_out, int out_size) {
    const float* t   = (const float*)d_in[0];
    const int*   t2e = (const int*)d_in[1];
    const int*   e2t = (const int*)d_in[2];
    const int*   t2n = (const int*)d_in[3];
    const int*   n2t = (const int*)d_in[4];
    const int*   eie = (const int*)d_in[5];
    const int*   ein = (const int*)d_in[6];
    const float* We  = (const float*)d_in[7];
    const float* be  = (const float*)d_in[8];
    const float* Wn  = (const float*)d_in[9];
    const float* bn  = (const float*)d_in[10];
    const float* ga  = (const float*)d_in[11];
    const float* gb  = (const float*)d_in[12];
    float* out = (float*)d_out;

    // g_deg arrives zeroed (module-load init + scan_k re-zeroes each call)
    degree_prep_k<<<256 + 1152, 1024>>>(eie, ein, We, Wn);
    scan_k<<<NPAIR, 1024>>>();
    fill_k<<<(NPAIR * EG) / 1024, 1024>>>(eie, ein);
    agg_copy_k<<<dim3(NSUB, NPAIR, 2), 192>>>(t, t2e, t2n, out);

    cudaFuncSetAttribute(gemm_k, cudaFuncAttributeMaxDynamicSharedMemorySize, 3 * 2 * STAGE_B);
    gemm_k<<<dim3(DDIM / 128, (BDIM * NSUB) / 128, 2), 128, 3 * 2 * STAGE_B>>>(
        be, bn, ga, gb, e2t, n2t, out);
}